// round 8
// baseline (speedup 1.0000x reference)
#include <cuda_runtime.h>
#include <cstdint>

// MemoryReader attention: SIMT fp32 logits/softmax + HMMA (mma.sync tf32) readout.
//   B=16, CK=64, CV=512, N=3136, 64 queries/CTA, 64-key tiles.
// Round 6: E stored transposed [q][k] pitch 68 -> B-fragment LDS conflict-free
// (was 4-way conflicted in [k][q] layout, the dominant smem-wavefront term).
// Denominator now accumulated via register partials + spread smem atomics.

#define Bsz     16
#define CKc     64
#define CVc     512
#define NPIX    3136
#define MQ      64
#define NT      64
#define THREADS 512
#define NTILES  (NPIX / NT)   // 49
#define PITCH   68            // V tile pitch (words): conflict-free frag LDS
#define EPITCH  68            // Et tile pitch (words): conflict-free B-frag LDS

typedef unsigned long long u64;

__device__ __forceinline__ uint32_t cvt_tf32(float f) {
    uint32_t r; asm("cvt.rna.tf32.f32 %0, %1;" : "=r"(r) : "f"(f)); return r;
}
__device__ __forceinline__ u64 pack2(float lo, float hi) {
    u64 r; asm("mov.b64 %0, {%1, %2};" : "=l"(r) : "f"(lo), "f"(hi)); return r;
}
__device__ __forceinline__ void unpack2(u64 v, float& lo, float& hi) {
    asm("mov.b64 {%0, %1}, %2;" : "=f"(lo), "=f"(hi) : "l"(v));
}
__device__ __forceinline__ u64 fma2(u64 a, u64 b, u64 c) {
    u64 d; asm("fma.rn.f32x2 %0, %1, %2, %3;" : "=l"(d) : "l"(a), "l"(b), "l"(c)); return d;
}
__device__ __forceinline__ void mma_tf32(float d[4], const uint32_t a[4], const uint32_t b[2]) {
    asm volatile(
        "mma.sync.aligned.m16n8k8.row.col.f32.tf32.tf32.f32 "
        "{%0,%1,%2,%3}, {%4,%5,%6,%7}, {%8,%9}, {%0,%1,%2,%3};"
        : "+f"(d[0]), "+f"(d[1]), "+f"(d[2]), "+f"(d[3])
        : "r"(a[0]), "r"(a[1]), "r"(a[2]), "r"(a[3]), "r"(b[0]), "r"(b[1]));
}

__global__ __launch_bounds__(THREADS, 1)
void mr_attn_kernel(const float* __restrict__ mk, const float* __restrict__ qk,
                    const float* __restrict__ mv, float* __restrict__ out)
{
    extern __shared__ float sm[];
    float* Qs = sm;                      // [64ck][64q]     4096 w (fp32)
    float* Ks = Qs + CKc * MQ;           // [64ck][64key]   4096 w (fp32)
    float* Et = Ks + CKc * NT;           // [64q][EPITCH]   4352 w (tf32 bits, TRANSPOSED)
    float* Vs = Et + MQ * EPITCH;        // [512ch][PITCH]  34816 w (tf32 bits)
    float* S2 = Vs + CVc * PITCH;        // [64]
    float* Dn = S2 + NT;                 // [64]

    const int b    = blockIdx.y;
    const int m0   = blockIdx.x * MQ;
    const int tid  = threadIdx.x;
    const int wid  = tid >> 5;
    const int lane = tid & 31;
    const int g    = lane >> 2;          // mma group row
    const int tq   = lane & 3;           // mma quad col

    const float* qb = qk + (size_t)b * CKc * NPIX + m0;
    const float* kb = mk + (size_t)b * CKc * NPIX;
    const float* vb = mv + (size_t)b * CVc * NPIX;

    // Q tile (fp32, SIMT logits)
    #pragma unroll
    for (int idx = tid; idx < CKc * (MQ / 4); idx += THREADS) {
        int c = idx >> 4, m4 = idx & 15;
        *(float4*)(Qs + c * MQ + 4 * m4) = *(const float4*)(qb + c * NPIX + 4 * m4);
    }
    if (tid < MQ) Dn[tid] = 0.f;

    // Accumulator fragments: 2 m-tiles (16ch) x 8 n-tiles (8q), 4 regs each
    float d[2][8][4];
    #pragma unroll
    for (int i = 0; i < 2; ++i)
        #pragma unroll
        for (int j = 0; j < 8; ++j)
            #pragma unroll
            for (int r = 0; r < 4; ++r) d[i][j][r] = 0.f;

    const int ch0 = wid * 32;            // warp's channel slab
    const int ln  = wid * 4;             // logits: 4 keys per thread
    const int lm  = lane * 2;            // logits: 2 queries per thread

    for (int t = 0; t < NTILES; ++t) {
        const int n0 = t * NT;
        __syncthreads();   // previous tile's frag reads done; tiles reusable

        // K tile (fp32 for logits)
        #pragma unroll
        for (int idx = tid; idx < CKc * (NT / 4); idx += THREADS) {
            int c = idx >> 4, n4 = idx & 15;
            *(float4*)(Ks + c * NT + 4 * n4) = *(const float4*)(kb + c * NPIX + n0 + 4 * n4);
        }
        // V tile -> tf32 bits, natural c-major layout, pitch 68
        #pragma unroll
        for (int idx = tid; idx < CVc * (NT / 4); idx += THREADS) {
            int c = idx >> 4, n4 = idx & 15;
            float4 v = *(const float4*)(vb + c * NPIX + n0 + 4 * n4);
            uint4 tv = make_uint4(cvt_tf32(v.x), cvt_tf32(v.y), cvt_tf32(v.z), cvt_tf32(v.w));
            *(uint4*)(Vs + c * PITCH + 4 * n4) = tv;
        }
        __syncthreads();

        // ||k||^2 per key
        if (tid < NT) {
            float s = 0.f;
            #pragma unroll
            for (int c = 0; c < CKc; ++c) { float k = Ks[c * NT + tid]; s = fmaf(k, k, s); }
            S2[tid] = s;
        }
        __syncthreads();

        // Logits + exp (fp32 FFMA2): 4 keys x 2 queries/thread; Et[q][k] <- tf32
        {
            u64 dot2[4] = {0ull, 0ull, 0ull, 0ull};
            #pragma unroll
            for (int c = 0; c < CKc; ++c) {
                float4 k4 = *(const float4*)(Ks + c * NT + ln);
                u64 qp = *(const u64*)(Qs + c * MQ + lm);
                dot2[0] = fma2(pack2(k4.x, k4.x), qp, dot2[0]);
                dot2[1] = fma2(pack2(k4.y, k4.y), qp, dot2[1]);
                dot2[2] = fma2(pack2(k4.z, k4.z), qp, dot2[2]);
                dot2[3] = fma2(pack2(k4.w, k4.w), qp, dot2[3]);
            }
            const float C1 = 0.125f * 1.4426950408889634f;  // log2(e)/sqrt(CK)
            float4 s4 = *(const float4*)(S2 + ln);
            float sb[4] = {s4.x * C1, s4.y * C1, s4.z * C1, s4.w * C1};
            float p0 = 0.f, p1 = 0.f;
            #pragma unroll
            for (int i = 0; i < 4; ++i) {
                float d0, d1; unpack2(dot2[i], d0, d1);
                float e0 = exp2f(fmaf(d0, 2.f * C1, -sb[i]));
                float e1 = exp2f(fmaf(d1, 2.f * C1, -sb[i]));
                p0 += e0; p1 += e1;
                Et[lm * EPITCH + ln + i]       = __uint_as_float(cvt_tf32(e0));
                Et[(lm + 1) * EPITCH + ln + i] = __uint_as_float(cvt_tf32(e1));
            }
            // denominator: register partials, spread smem atomics (distinct addr/warp)
            atomicAdd(&Dn[lm],     p0);
            atomicAdd(&Dn[lm + 1], p1);
        }
        __syncthreads();

        // Readout: D[32ch x 64q] += V[32ch x 64k] * E[64k x 64q] via HMMA tf32
        // A-frag banks: (4g+tq) bijective -> conflict-free.
        // B-frag banks: Et[(j*8+g)*68 + k0+tq] -> (4g+tq+k0)%32 -> conflict-free.
        const uint32_t* Vu = (const uint32_t*)Vs;
        const uint32_t* Eu = (const uint32_t*)Et;
        #pragma unroll
        for (int s = 0; s < 8; ++s) {               // k-step of 8
            const int k0 = s * 8;
            uint32_t a[2][4];
            #pragma unroll
            for (int i = 0; i < 2; ++i) {
                int row = ch0 + 16 * i + g;
                a[i][0] = Vu[row * PITCH + k0 + tq];
                a[i][1] = Vu[(row + 8) * PITCH + k0 + tq];
                a[i][2] = Vu[row * PITCH + k0 + tq + 4];
                a[i][3] = Vu[(row + 8) * PITCH + k0 + tq + 4];
            }
            uint32_t bfr[8][2];
            #pragma unroll
            for (int j = 0; j < 8; ++j) {
                int q = j * 8 + g;
                bfr[j][0] = Eu[q * EPITCH + k0 + tq];
                bfr[j][1] = Eu[q * EPITCH + k0 + tq + 4];
            }
            #pragma unroll
            for (int i = 0; i < 2; ++i)
                #pragma unroll
                for (int j = 0; j < 8; ++j)
                    mma_tf32(d[i][j], a[i], bfr[j]);
        }
    }
    __syncthreads();
    if (tid < MQ) Dn[tid] = 1.0f / Dn[tid];
    __syncthreads();

    // Epilogue: scale by 1/denominator, store
    #pragma unroll
    for (int i = 0; i < 2; ++i) {
        int ch = ch0 + 16 * i + g;
        float* op0 = out + ((size_t)b * CVc + ch) * NPIX + m0;
        float* op1 = out + ((size_t)b * CVc + ch + 8) * NPIX + m0;
        #pragma unroll
        for (int j = 0; j < 8; ++j) {
            int q = j * 8 + 2 * tq;
            float2 dn2 = *(const float2*)(Dn + q);
            float2 o0 = make_float2(d[i][j][0] * dn2.x, d[i][j][1] * dn2.y);
            float2 o1 = make_float2(d[i][j][2] * dn2.x, d[i][j][3] * dn2.y);
            *(float2*)(op0 + q) = o0;
            *(float2*)(op1 + q) = o1;
        }
    }
}

extern "C" void kernel_launch(void* const* d_in, const int* in_sizes, int n_in,
                              void* d_out, int out_size)
{
    const float* mk = (const float*)d_in[0];
    const float* qk = (const float*)d_in[1];
    const float* mv = (const float*)d_in[2];
    const float* qv = (const float*)d_in[3];
    float* out = (float*)d_out;

    size_t smem = (size_t)(CKc * MQ + CKc * NT + MQ * EPITCH + CVc * PITCH + NT + MQ)
                  * sizeof(float);
    cudaFuncSetAttribute(mr_attn_kernel, cudaFuncAttributeMaxDynamicSharedMemorySize, (int)smem);

    dim3 grid(NPIX / MQ, Bsz);   // 49 x 16
    mr_attn_kernel<<<grid, THREADS, smem>>>(mk, qk, mv, out);

    size_t memElems = (size_t)Bsz * CVc * NPIX;
    if ((size_t)out_size >= 2 * memElems) {
        cudaMemcpyAsync(out + memElems, qv, memElems * sizeof(float),
                        cudaMemcpyDeviceToDevice);
    }
}